// round 1
// baseline (speedup 1.0000x reference)
#include <cuda_runtime.h>
#include <math.h>
#include <stdint.h>

#define NLEV 16
#define THASH (1u << 19)
#define BLK 256
#define ACT_STRIDE 68
#define WTOT 10436  // 2048 (w0) + 4096 (w1) + 4096 (w2) + 192 (w_out) + 4 (b_out pad)

struct Res4 { int v[NLEV][4]; };

__device__ __forceinline__ float dot32(const float* __restrict__ f, const float* __restrict__ w) {
    float acc = 0.f;
    #pragma unroll
    for (int k = 0; k < 8; k++) {
        float4 wv = ((const float4*)w)[k];
        acc = fmaf(f[4*k+0], wv.x, acc);
        acc = fmaf(f[4*k+1], wv.y, acc);
        acc = fmaf(f[4*k+2], wv.z, acc);
        acc = fmaf(f[4*k+3], wv.w, acc);
    }
    return acc;
}

__device__ __forceinline__ float dot64(const float* __restrict__ f, const float* __restrict__ w) {
    float acc = 0.f;
    #pragma unroll
    for (int k = 0; k < 16; k++) {
        float4 wv = ((const float4*)w)[k];
        acc = fmaf(f[4*k+0], wv.x, acc);
        acc = fmaf(f[4*k+1], wv.y, acc);
        acc = fmaf(f[4*k+2], wv.z, acc);
        acc = fmaf(f[4*k+3], wv.w, acc);
    }
    return acc;
}

__global__ void __launch_bounds__(BLK)
ingp_fused(const float* __restrict__ x,
           const float2* __restrict__ table,
           const float* __restrict__ w0,
           const float* __restrict__ w1,
           const float* __restrict__ w2,
           const float* __restrict__ w_out,
           const float* __restrict__ b_out,
           float* __restrict__ out,
           int N, Res4 res)
{
    extern __shared__ float sm[];
    float* s_w0 = sm;                         // 2048
    float* s_w1 = sm + 2048;                  // 4096
    float* s_w2 = sm + 2048 + 4096;           // 4096
    float* s_wo = sm + 2048 + 4096 + 4096;    // 192
    float* s_bo = s_wo + 192;                 // 3 (+1 pad)
    float* s_act = sm + WTOT;                 // BLK * ACT_STRIDE

    const int tid = threadIdx.x;

    // cooperative weight load (vectorized)
    {
        float4* dw0 = (float4*)s_w0; const float4* sw0 = (const float4*)w0;
        float4* dw1 = (float4*)s_w1; const float4* sw1 = (const float4*)w1;
        float4* dw2 = (float4*)s_w2; const float4* sw2 = (const float4*)w2;
        float4* dwo = (float4*)s_wo; const float4* swo = (const float4*)w_out;
        #pragma unroll 1
        for (int i = tid; i < 512;  i += BLK) dw0[i] = sw0[i];
        #pragma unroll 1
        for (int i = tid; i < 1024; i += BLK) dw1[i] = sw1[i];
        #pragma unroll 1
        for (int i = tid; i < 1024; i += BLK) dw2[i] = sw2[i];
        if (tid < 48) dwo[tid] = swo[tid];
        if (tid < 3)  s_bo[tid] = b_out[tid];
    }
    __syncthreads();

    const int n = blockIdx.x * BLK + tid;
    if (n >= N) return;

    float* arow = s_act + tid * ACT_STRIDE;
    const float4 xv = ((const float4*)x)[n];

    // ---------------- multi-res 4D hash encode ----------------
    #pragma unroll 1
    for (int l = 0; l < NLEV; l++) {
        const float r0 = (float)res.v[l][0] - 1.0f;
        const float r1 = (float)res.v[l][1] - 1.0f;
        const float r2 = (float)res.v[l][2] - 1.0f;
        const float r3 = (float)res.v[l][3] - 1.0f;
        float p0 = xv.x * r0, p1 = xv.y * r1, p2 = xv.z * r2, p3 = xv.w * r3;
        float b0 = floorf(p0), b1 = floorf(p1), b2 = floorf(p2), b3 = floorf(p3);
        float f0 = p0 - b0, f1 = p1 - b1, f2 = p2 - b2, f3 = p3 - b3;
        float g0 = 1.f - f0, g1 = 1.f - f1, g2 = 1.f - f2, g3 = 1.f - f3;

        // per-dim hash terms (PRIMES = {1, 2654435761, 805459861, 3674653429}), u32 wrap
        unsigned ha0 = (unsigned)(int)b0;                 unsigned hb0 = ha0 + 1u;
        unsigned ha1 = (unsigned)(int)b1 * 2654435761u;   unsigned hb1 = ha1 + 2654435761u;
        unsigned ha2 = (unsigned)(int)b2 * 805459861u;    unsigned hb2 = ha2 + 805459861u;
        unsigned ha3 = (unsigned)(int)b3 * 3674653429u;   unsigned hb3 = ha3 + 3674653429u;

        unsigned hxy[4] = { ha0 ^ ha1, hb0 ^ ha1, ha0 ^ hb1, hb0 ^ hb1 };
        unsigned hzw[4] = { ha2 ^ ha3, hb2 ^ ha3, ha2 ^ hb3, hb2 ^ hb3 };
        float    wxy[4] = { g0 * g1,  f0 * g1,  g0 * f1,  f0 * f1 };
        float    wzw[4] = { g2 * g3,  f2 * g3,  g2 * f3,  f2 * f3 };

        const float2* tl = table + ((size_t)l << 19);
        float acc0 = 0.f, acc1 = 0.f;
        #pragma unroll
        for (int c = 0; c < 16; c++) {
            unsigned idx = (hxy[c & 3] ^ hzw[(c >> 2) & 3]) & (THASH - 1u);
            float2 t2 = __ldg(tl + idx);
            float w = wxy[c & 3] * wzw[(c >> 2) & 3];
            acc0 = fmaf(w, t2.x, acc0);
            acc1 = fmaf(w, t2.y, acc1);
        }
        arow[2*l]     = acc0;
        arow[2*l + 1] = acc1;
    }

    // ---------------- MLP: 32 -> 64 -> 64 -> 64 -> 3 ----------------
    float f[64];

    // layer 0: 32 -> 64, ReLU
    #pragma unroll
    for (int k = 0; k < 8; k++) {
        float4 v = ((const float4*)arow)[k];
        f[4*k] = v.x; f[4*k+1] = v.y; f[4*k+2] = v.z; f[4*k+3] = v.w;
    }
    #pragma unroll 1
    for (int j = 0; j < 64; j += 4) {
        float a0 = dot32(f, s_w0 + (j + 0) * 32);
        float a1 = dot32(f, s_w0 + (j + 1) * 32);
        float a2 = dot32(f, s_w0 + (j + 2) * 32);
        float a3 = dot32(f, s_w0 + (j + 3) * 32);
        ((float4*)arow)[j >> 2] = make_float4(fmaxf(a0, 0.f), fmaxf(a1, 0.f),
                                              fmaxf(a2, 0.f), fmaxf(a3, 0.f));
    }

    // layer 1: 64 -> 64, ReLU
    #pragma unroll
    for (int k = 0; k < 16; k++) {
        float4 v = ((const float4*)arow)[k];
        f[4*k] = v.x; f[4*k+1] = v.y; f[4*k+2] = v.z; f[4*k+3] = v.w;
    }
    #pragma unroll 1
    for (int j = 0; j < 64; j += 4) {
        float a0 = dot64(f, s_w1 + (j + 0) * 64);
        float a1 = dot64(f, s_w1 + (j + 1) * 64);
        float a2 = dot64(f, s_w1 + (j + 2) * 64);
        float a3 = dot64(f, s_w1 + (j + 3) * 64);
        ((float4*)arow)[j >> 2] = make_float4(fmaxf(a0, 0.f), fmaxf(a1, 0.f),
                                              fmaxf(a2, 0.f), fmaxf(a3, 0.f));
    }

    // layer 2: 64 -> 64, ReLU
    #pragma unroll
    for (int k = 0; k < 16; k++) {
        float4 v = ((const float4*)arow)[k];
        f[4*k] = v.x; f[4*k+1] = v.y; f[4*k+2] = v.z; f[4*k+3] = v.w;
    }
    #pragma unroll 1
    for (int j = 0; j < 64; j += 4) {
        float a0 = dot64(f, s_w2 + (j + 0) * 64);
        float a1 = dot64(f, s_w2 + (j + 1) * 64);
        float a2 = dot64(f, s_w2 + (j + 2) * 64);
        float a3 = dot64(f, s_w2 + (j + 3) * 64);
        ((float4*)arow)[j >> 2] = make_float4(fmaxf(a0, 0.f), fmaxf(a1, 0.f),
                                              fmaxf(a2, 0.f), fmaxf(a3, 0.f));
    }

    // output layer: 64 -> 3, + bias
    #pragma unroll
    for (int k = 0; k < 16; k++) {
        float4 v = ((const float4*)arow)[k];
        f[4*k] = v.x; f[4*k+1] = v.y; f[4*k+2] = v.z; f[4*k+3] = v.w;
    }
    float o0 = s_bo[0] + dot64(f, s_wo + 0);
    float o1 = s_bo[1] + dot64(f, s_wo + 64);
    float o2 = s_bo[2] + dot64(f, s_wo + 128);

    const size_t ob = (size_t)n * 3;
    out[ob + 0] = o0;
    out[ob + 1] = o1;
    out[ob + 2] = o2;
}

extern "C" void kernel_launch(void* const* d_in, const int* in_sizes, int n_in,
                              void* d_out, int out_size)
{
    const float*  x      = (const float*)d_in[0];
    const float2* table  = (const float2*)d_in[1];
    const float*  w0     = (const float*)d_in[2];
    const float*  w1     = (const float*)d_in[3];
    const float*  w2     = (const float*)d_in[4];
    const float*  w_out  = (const float*)d_in[5];
    const float*  b_out  = (const float*)d_in[6];
    float* out = (float*)d_out;
    const int N = in_sizes[0] / 4;

    // Replicate numpy's RES computation bit-exactly: same aarch64 glibc pow/floor
    // as the reference process uses (numpy npy_pow falls through to libm pow).
    Res4 res;
    const double minr[4] = {16.0, 16.0, 16.0, 16.0};
    const double maxr[4] = {256.0, 256.0, 256.0, 128.0};
    for (int d = 0; d < 4; d++) {
        double g = pow(maxr[d] / minr[d], 1.0 / 15.0);
        for (int l = 0; l < NLEV; l++) {
            res.v[l][d] = (int)floor(minr[d] * pow(g, (double)l));
        }
    }

    size_t smem = (size_t)(WTOT + BLK * ACT_STRIDE) * sizeof(float);
    cudaFuncSetAttribute(ingp_fused, cudaFuncAttributeMaxDynamicSharedMemorySize, (int)smem);

    int grid = (N + BLK - 1) / BLK;
    ingp_fused<<<grid, BLK, smem>>>(x, table, w0, w1, w2, w_out, b_out, out, N, res);
}

// round 2
// speedup vs baseline: 1.0703x; 1.0703x over previous
#include <cuda_runtime.h>
#include <math.h>
#include <stdint.h>

#define NLEV 16
#define THASH (1u << 19)
#define BLK 256
#define ACT_STRIDE 68

struct Res4 { int v[NLEV][4]; };

// MLP weights in the constant bank: read via LDC (constant-cache port),
// completely off the L1tex pipe that the hash gathers saturate.
__constant__ float cW0[64 * 32];
__constant__ float cW1[64 * 64];
__constant__ float cW2[64 * 64];
__constant__ float cWo[3 * 64];
__constant__ float cBo[3];

__global__ void __launch_bounds__(BLK, 2)
ingp_fused(const float* __restrict__ x,
           const float2* __restrict__ table,
           float* __restrict__ out,
           int N, Res4 res)
{
    extern __shared__ float s_act[];
    const int tid = threadIdx.x;
    const int n = blockIdx.x * BLK + tid;
    if (n >= N) return;

    float* arow = s_act + tid * ACT_STRIDE;
    const float4 xv = __ldg((const float4*)x + n);

    // ---------------- multi-res 4D hash encode (fully unrolled) ----------------
    float feat[32];
    #pragma unroll
    for (int l = 0; l < NLEV; l++) {
        const float r0 = (float)res.v[l][0] - 1.0f;
        const float r1 = (float)res.v[l][1] - 1.0f;
        const float r2 = (float)res.v[l][2] - 1.0f;
        const float r3 = (float)res.v[l][3] - 1.0f;
        float p0 = xv.x * r0, p1 = xv.y * r1, p2 = xv.z * r2, p3 = xv.w * r3;
        float b0 = floorf(p0), b1 = floorf(p1), b2 = floorf(p2), b3 = floorf(p3);
        float f0 = p0 - b0, f1 = p1 - b1, f2 = p2 - b2, f3 = p3 - b3;
        float g0 = 1.f - f0, g1 = 1.f - f1, g2 = 1.f - f2, g3 = 1.f - f3;

        unsigned ha0 = (unsigned)(int)b0;                 unsigned hb0 = ha0 + 1u;
        unsigned ha1 = (unsigned)(int)b1 * 2654435761u;   unsigned hb1 = ha1 + 2654435761u;
        unsigned ha2 = (unsigned)(int)b2 * 805459861u;    unsigned hb2 = ha2 + 805459861u;
        unsigned ha3 = (unsigned)(int)b3 * 3674653429u;   unsigned hb3 = ha3 + 3674653429u;

        unsigned hxy[4] = { ha0 ^ ha1, hb0 ^ ha1, ha0 ^ hb1, hb0 ^ hb1 };
        unsigned hzw[4] = { ha2 ^ ha3, hb2 ^ ha3, ha2 ^ hb3, hb2 ^ hb3 };
        float    wxy[4] = { g0 * g1,  f0 * g1,  g0 * f1,  f0 * f1 };
        float    wzw[4] = { g2 * g3,  f2 * g3,  g2 * f3,  f2 * f3 };

        const float2* tl = table + ((size_t)l << 19);
        float acc0 = 0.f, acc1 = 0.f;
        #pragma unroll
        for (int c = 0; c < 16; c++) {
            unsigned idx = (hxy[c & 3] ^ hzw[(c >> 2) & 3]) & (THASH - 1u);
            float2 t2 = __ldg(tl + idx);
            float w = wxy[c & 3] * wzw[(c >> 2) & 3];
            acc0 = fmaf(w, t2.x, acc0);
            acc1 = fmaf(w, t2.y, acc1);
        }
        feat[2*l]     = acc0;
        feat[2*l + 1] = acc1;
    }

    // ---------------- MLP: 32 -> 64 -> 64 -> 64 -> 3 (weights via LDC) --------

    // layer 0: input straight from registers, output -> smem row
    #pragma unroll 1
    for (int j = 0; j < 64; j += 4) {
        float a0 = 0.f, a1 = 0.f, a2 = 0.f, a3 = 0.f;
        #pragma unroll
        for (int k = 0; k < 32; k++) {
            float fv = feat[k];
            a0 = fmaf(fv, cW0[(j + 0) * 32 + k], a0);
            a1 = fmaf(fv, cW0[(j + 1) * 32 + k], a1);
            a2 = fmaf(fv, cW0[(j + 2) * 32 + k], a2);
            a3 = fmaf(fv, cW0[(j + 3) * 32 + k], a3);
        }
        ((float4*)arow)[j >> 2] = make_float4(fmaxf(a0, 0.f), fmaxf(a1, 0.f),
                                              fmaxf(a2, 0.f), fmaxf(a3, 0.f));
    }

    float f[64];

    // layer 1: 64 -> 64, ReLU
    #pragma unroll
    for (int k = 0; k < 16; k++) {
        float4 v = ((const float4*)arow)[k];
        f[4*k] = v.x; f[4*k+1] = v.y; f[4*k+2] = v.z; f[4*k+3] = v.w;
    }
    #pragma unroll 1
    for (int j = 0; j < 64; j += 4) {
        float a0 = 0.f, a1 = 0.f, a2 = 0.f, a3 = 0.f;
        #pragma unroll
        for (int k = 0; k < 64; k++) {
            float fv = f[k];
            a0 = fmaf(fv, cW1[(j + 0) * 64 + k], a0);
            a1 = fmaf(fv, cW1[(j + 1) * 64 + k], a1);
            a2 = fmaf(fv, cW1[(j + 2) * 64 + k], a2);
            a3 = fmaf(fv, cW1[(j + 3) * 64 + k], a3);
        }
        ((float4*)arow)[j >> 2] = make_float4(fmaxf(a0, 0.f), fmaxf(a1, 0.f),
                                              fmaxf(a2, 0.f), fmaxf(a3, 0.f));
    }

    // layer 2: 64 -> 64, ReLU
    #pragma unroll
    for (int k = 0; k < 16; k++) {
        float4 v = ((const float4*)arow)[k];
        f[4*k] = v.x; f[4*k+1] = v.y; f[4*k+2] = v.z; f[4*k+3] = v.w;
    }
    #pragma unroll 1
    for (int j = 0; j < 64; j += 4) {
        float a0 = 0.f, a1 = 0.f, a2 = 0.f, a3 = 0.f;
        #pragma unroll
        for (int k = 0; k < 64; k++) {
            float fv = f[k];
            a0 = fmaf(fv, cW2[(j + 0) * 64 + k], a0);
            a1 = fmaf(fv, cW2[(j + 1) * 64 + k], a1);
            a2 = fmaf(fv, cW2[(j + 2) * 64 + k], a2);
            a3 = fmaf(fv, cW2[(j + 3) * 64 + k], a3);
        }
        ((float4*)arow)[j >> 2] = make_float4(fmaxf(a0, 0.f), fmaxf(a1, 0.f),
                                              fmaxf(a2, 0.f), fmaxf(a3, 0.f));
    }

    // output layer: 64 -> 3, + bias
    #pragma unroll
    for (int k = 0; k < 16; k++) {
        float4 v = ((const float4*)arow)[k];
        f[4*k] = v.x; f[4*k+1] = v.y; f[4*k+2] = v.z; f[4*k+3] = v.w;
    }
    float o0 = cBo[0], o1 = cBo[1], o2 = cBo[2];
    #pragma unroll
    for (int k = 0; k < 64; k++) {
        float fv = f[k];
        o0 = fmaf(fv, cWo[0 * 64 + k], o0);
        o1 = fmaf(fv, cWo[1 * 64 + k], o1);
        o2 = fmaf(fv, cWo[2 * 64 + k], o2);
    }

    const size_t ob = (size_t)n * 3;
    out[ob + 0] = o0;
    out[ob + 1] = o1;
    out[ob + 2] = o2;
}

extern "C" void kernel_launch(void* const* d_in, const int* in_sizes, int n_in,
                              void* d_out, int out_size)
{
    const float*  x      = (const float*)d_in[0];
    const float2* table  = (const float2*)d_in[1];
    float* out = (float*)d_out;
    const int N = in_sizes[0] / 4;

    // Weights -> constant bank (graph-capturable D2D memcpy nodes)
    cudaMemcpyToSymbolAsync(cW0, d_in[2], 64 * 32 * sizeof(float), 0, cudaMemcpyDeviceToDevice, 0);
    cudaMemcpyToSymbolAsync(cW1, d_in[3], 64 * 64 * sizeof(float), 0, cudaMemcpyDeviceToDevice, 0);
    cudaMemcpyToSymbolAsync(cW2, d_in[4], 64 * 64 * sizeof(float), 0, cudaMemcpyDeviceToDevice, 0);
    cudaMemcpyToSymbolAsync(cWo, d_in[5], 3 * 64 * sizeof(float), 0, cudaMemcpyDeviceToDevice, 0);
    cudaMemcpyToSymbolAsync(cBo, d_in[6], 3 * sizeof(float), 0, cudaMemcpyDeviceToDevice, 0);

    // Replicate numpy's RES computation bit-exactly (same aarch64 glibc pow/floor).
    Res4 res;
    const double minr[4] = {16.0, 16.0, 16.0, 16.0};
    const double maxr[4] = {256.0, 256.0, 256.0, 128.0};
    for (int d = 0; d < 4; d++) {
        double g = pow(maxr[d] / minr[d], 1.0 / 15.0);
        for (int l = 0; l < NLEV; l++) {
            res.v[l][d] = (int)floor(minr[d] * pow(g, (double)l));
        }
    }

    size_t smem = (size_t)(BLK * ACT_STRIDE) * sizeof(float);
    cudaFuncSetAttribute(ingp_fused, cudaFuncAttributeMaxDynamicSharedMemorySize, (int)smem);

    int grid = (N + BLK - 1) / BLK;
    ingp_fused<<<grid, BLK, smem>>>(x, table, out, N, res);
}